// round 16
// baseline (speedup 1.0000x reference)
#include <cuda_runtime.h>
#include <cuda_bf16.h>
#include <cstdint>

#define NNODES 50000
#define EMAX   800000
#define SBLK   ((NNODES + 1023) / 1024)   // 49 scan blocks
#define EB     ((EMAX + 255) / 256)       // 3125 edge blocks (E is always 800000)

// ---------------- device scratch ----------------
struct ZeroRegion {
    int deg[NNODES];
    unsigned long long lb[64];            // lookback words: (val<<2)|state
};
__device__ ZeroRegion g_z;

__device__ int g_rowstart[NNODES + 1];
__device__ int g_csr_src[EMAX];
__device__ __align__(128) float g_cat[(size_t)NNODES * 256]; // L1 A=[agg|x]; L2 reuse: Pself fp32 [N,128]
__device__ __align__(128) float g_h[(size_t)NNODES * 256];   // hidden activations (tf32-rounded)
__device__ __align__(128) __nv_bfloat16 g_x16[(size_t)NNODES * 128]; // bf16 copy of x (gather table)
__device__ __align__(128) __nv_bfloat16 g_P16[(size_t)NNODES * 128]; // bf16 agg-half of P (gather table)
__device__ __align__(128) float g_Bp1[256 * 256];            // packed tf32 weights layer1
__device__ __align__(128) float g_Bp2[256 * 256];            // packed tf32 weights layer2

__device__ __forceinline__ float to_tf32(float x) {
    float r;
    asm("cvt.rna.tf32.f32 %0, %1;" : "=f"(r) : "f"(x));
    return r;
}

// per-block dtype detect: int32 data read as u64 has nonzero high halves
__device__ __forceinline__ int block_detect_is32(const void* eidx) {
    __shared__ int s_is32;
    if (threadIdx.x < 32) {
        const unsigned long long* p = (const unsigned long long*)eidx;
        bool big = (p[threadIdx.x] > 0xFFFFFFFFULL) ||
                   (p[threadIdx.x + 32] > 0xFFFFFFFFULL);
        unsigned bal = __ballot_sync(0xFFFFFFFFu, big);
        if (threadIdx.x == 0) s_is32 = bal ? 1 : 0;
    }
    __syncthreads();
    return s_is32;
}

__device__ __forceinline__ long long edge_val(const void* eidx, long long idx, int is32) {
    if (is32) return (long long)((const int*)eidx)[idx];
    return ((const long long*)eidx)[idx];
}

// ---------------- fused prologue: count_deg | pack | convert_x -------------
__global__ void fused_prologue_kernel(
    const void* eidx, long long E, const float* __restrict__ x,
    const float* __restrict__ W1l, const float* __restrict__ W1r,
    const float* __restrict__ W2l, const float* __restrict__ W2r)
{
    int b = blockIdx.x;
    if (b < EB) {
        int is32 = block_detect_is32(eidx);
        long long e = (long long)b * 256 + threadIdx.x;
        if (e < E) {
            int d = (int)edge_val(eidx, E + e, is32);
            atomicAdd(&g_z.deg[d], 1);
        }
    } else if (b < EB + 512) {
        int i = (b - EB) * 256 + threadIdx.x;
        if (i < 65536) {
            int n = i >> 8, k = i & 255;
            float v = (k < 128) ? W1l[n * 128 + k] : W1r[n * 128 + (k - 128)];
            g_Bp1[i] = to_tf32(v);
        } else {
            int j = i - 65536;
            int n = j >> 8, k = j & 255;
            float v = (n < 128) ? W2l[n * 256 + k] : W2r[(n - 128) * 256 + k];
            g_Bp2[j] = to_tf32(v);
        }
    } else {
        int i = (b - EB - 512) * 256 + threadIdx.x;   // one per 4 elems
        if (i < NNODES * 32) {
            float4 v = ((const float4*)x)[i];
            __nv_bfloat162 a = __floats2bfloat162_rn(v.x, v.y);
            __nv_bfloat162 bb = __floats2bfloat162_rn(v.z, v.w);
            uint2 q;
            q.x = *(uint32_t*)&a;
            q.y = *(uint32_t*)&bb;
            ((uint2*)g_x16)[i] = q;
        }
    }
}

// single-pass scan with decoupled lookback (49 blocks, all co-resident)
__global__ void scan_lookback_kernel(int nblk) {
    __shared__ int wsum[32];
    __shared__ int s_run;
    int b = blockIdx.x, t = threadIdx.x;
    int i = b * 1024 + t;
    int v = (i < NNODES) ? g_z.deg[i] : 0;
    int lane = t & 31, wid = t >> 5;
    int x = v;
    #pragma unroll
    for (int o = 1; o < 32; o <<= 1) {
        int y = __shfl_up_sync(0xFFFFFFFFu, x, o);
        if (lane >= o) x += y;
    }
    if (lane == 31) wsum[wid] = x;
    __syncthreads();
    if (wid == 0) {
        int s = wsum[lane];
        #pragma unroll
        for (int o = 1; o < 32; o <<= 1) {
            int y = __shfl_up_sync(0xFFFFFFFFu, s, o);
            if (lane >= o) s += y;
        }
        wsum[lane] = s;
    }
    __syncthreads();
    int blockSum = wsum[31];
    int excl = x - v + (wid ? wsum[wid - 1] : 0);

    if (t == 0) {
        atomicExch(&g_z.lb[b], ((unsigned long long)blockSum << 2) | 1ULL);
        long long run = 0;
        for (int j = b - 1; j >= 0; ) {
            unsigned long long w;
            do { w = atomicAdd(&g_z.lb[j], 0ULL); } while ((w & 3ULL) == 0ULL);
            run += (long long)(w >> 2);
            if ((w & 3ULL) == 2ULL) break;
            j--;
        }
        atomicExch(&g_z.lb[b], ((unsigned long long)(blockSum + run) << 2) | 2ULL);
        s_run = (int)run;
        if (b == nblk - 1) g_rowstart[NNODES] = (int)run + blockSum;
    }
    __syncthreads();
    if (i < NNODES) g_rowstart[i] = excl + s_run;
}

// cursor-free scatter: rowstart doubles as the insertion cursor.
// After this kernel, g_rowstart[d] == old exclusive prefix of (d+1),
// so consumers use start = rowstart[node-1] (0 for node 0), end = rowstart[node].
__global__ void scatter_kernel(const void* eidx, long long E) {
    int is32 = block_detect_is32(eidx);
    long long e = (long long)blockIdx.x * blockDim.x + threadIdx.x;
    if (e >= E) return;
    int s = (int)edge_val(eidx, e, is32);
    int d = (int)edge_val(eidx, E + e, is32);
    int pos = atomicAdd(&g_rowstart[d], 1);
    g_csr_src[pos] = s;
}

// ---------------- gather helper: 4 bf16 (uint2) -> float4 accumulate ------
__device__ __forceinline__ void acc_bf16(float4& acc, uint2 q) {
    float2 f0 = __bfloat1622float2(*(__nv_bfloat162*)&q.x);
    float2 f1 = __bfloat1622float2(*(__nv_bfloat162*)&q.y);
    acc.x += f0.x; acc.y += f0.y; acc.z += f1.x; acc.w += f1.y;
}

// ---------------- layer-1 aggregation: 2 warps per node --------------------
// Block = 256 thr = 8 warps = 4 nodes. Warp pair (2p, 2p+1) handles node p:
// sub-warp s accumulates edges start+s, start+s+2, ... (unroll 4, stride 8).
// Combine via smem, sub 0 finalizes (agg tf32) + copies self half.
__global__ void agg_cat_kernel(const float* __restrict__ x, float* __restrict__ cat) {
    __shared__ float4 s_acc[4][32];
    int wid = threadIdx.x >> 5;
    int pair = wid >> 1, sub = wid & 1;
    int lane = threadIdx.x & 31;
    int node = blockIdx.x * 4 + pair;          // always < NNODES (50000 % 4 == 0)
    int start = node ? g_rowstart[node - 1] : 0;
    int end = g_rowstart[node];

    float4 acc = make_float4(0.f, 0.f, 0.f, 0.f);
    int e = start + sub;
    for (; e + 6 < end; e += 8) {
        int s0 = g_csr_src[e],     s1 = g_csr_src[e + 2];
        int s2 = g_csr_src[e + 4], s3 = g_csr_src[e + 6];
        uint2 q0 = ((const uint2*)(g_x16 + (size_t)s0 * 128))[lane];
        uint2 q1 = ((const uint2*)(g_x16 + (size_t)s1 * 128))[lane];
        uint2 q2 = ((const uint2*)(g_x16 + (size_t)s2 * 128))[lane];
        uint2 q3 = ((const uint2*)(g_x16 + (size_t)s3 * 128))[lane];
        acc_bf16(acc, q0); acc_bf16(acc, q1); acc_bf16(acc, q2); acc_bf16(acc, q3);
    }
    for (; e < end; e += 2) {
        uint2 q = ((const uint2*)(g_x16 + (size_t)g_csr_src[e] * 128))[lane];
        acc_bf16(acc, q);
    }
    if (sub == 1) s_acc[pair][lane] = acc;
    __syncthreads();
    if (sub == 0) {
        float4 o = s_acc[pair][lane];
        acc.x += o.x; acc.y += o.y; acc.z += o.z; acc.w += o.w;
        int deg = end - start;
        float inv = (deg > 0) ? 1.0f / (float)deg : 0.0f;
        float4* crow = (float4*)(cat + (size_t)node * 256);
        crow[lane] = make_float4(to_tf32(acc.x * inv), to_tf32(acc.y * inv),
                                 to_tf32(acc.z * inv), to_tf32(acc.w * inv));
        float4 xs = ((const float4*)(x + (size_t)node * 128))[lane];   // self: exact fp32
        crow[32 + lane] = make_float4(to_tf32(xs.x), to_tf32(xs.y),
                                      to_tf32(xs.z), to_tf32(xs.w));
    }
}

// ---------------- tf32 tensor-core GEMM, 2-stage cp.async pipeline ----------
// A[M,256] @ B[256,256]^T. mode=1: +bias,+relu,+tf32 round -> outf[M,256].
// mode=0 (layer2): bN==0 half -> bf16 to g_P16[M,128]; bN==128 half -> fp32 outf[M,128].
#define SM_STRIDE 36
#define STAGE_FLOATS (128 * SM_STRIDE)
#define GEMM_SMEM_BYTES (4 * STAGE_FLOATS * 4)

__device__ __forceinline__ void mma_tf32(float c[4], uint32_t a0, uint32_t a1,
                                         uint32_t a2, uint32_t a3,
                                         uint32_t b0, uint32_t b1) {
    asm volatile(
        "mma.sync.aligned.m16n8k8.row.col.f32.tf32.tf32.f32 "
        "{%0,%1,%2,%3}, {%4,%5,%6,%7}, {%8,%9}, {%0,%1,%2,%3};"
        : "+f"(c[0]), "+f"(c[1]), "+f"(c[2]), "+f"(c[3])
        : "r"(a0), "r"(a1), "r"(a2), "r"(a3), "r"(b0), "r"(b1));
}

__global__ void __launch_bounds__(256, 2) gemm_tf32_kernel(
    const float* __restrict__ A, const float* __restrict__ B,
    const float* __restrict__ bias, float* __restrict__ outf,
    int M, int mode)
{
    extern __shared__ float sm[];

    int tid = threadIdx.x;
    int lane = tid & 31, warp = tid >> 5;
    int wm = (warp >> 2) * 64;
    int wn = (warp & 3) * 32;
    int bM = blockIdx.y * 128;
    int bN = blockIdx.x * 128;
    int r = lane >> 2, cc = lane & 3;

    uint32_t sbase = (uint32_t)__cvta_generic_to_shared(sm);

    float c[4][4][4];
    #pragma unroll
    for (int mt = 0; mt < 4; mt++)
        #pragma unroll
        for (int nt = 0; nt < 4; nt++)
            #pragma unroll
            for (int q = 0; q < 4; q++) c[mt][nt][q] = 0.f;

    auto load_tile = [&](int kt, int s) {
        int k0 = kt * 32;
        #pragma unroll
        for (int i = 0; i < 4; i++) {
            int idx = i * 256 + tid;       // 0..1023
            int m = idx >> 3;              // 0..127
            int k4 = (idx & 7) * 4;        // 0..28
            const float* ga = A + (size_t)(bM + m) * 256 + k0 + k4;
            uint32_t da = sbase + (uint32_t)((s * STAGE_FLOATS + m * SM_STRIDE + k4) * 4);
            int sz = (bM + m < M) ? 16 : 0;
            asm volatile("cp.async.cg.shared.global [%0], [%1], 16, %2;"
                         :: "r"(da), "l"(ga), "r"(sz));
            const float* gb = B + (size_t)(bN + m) * 256 + k0 + k4;
            uint32_t db = sbase + (uint32_t)(((2 + s) * STAGE_FLOATS + m * SM_STRIDE + k4) * 4);
            asm volatile("cp.async.cg.shared.global [%0], [%1], 16, %2;"
                         :: "r"(db), "l"(gb), "r"(16));
        }
        asm volatile("cp.async.commit_group;");
    };

    load_tile(0, 0);

    for (int kt = 0; kt < 8; kt++) {
        if (kt + 1 < 8) {
            load_tile(kt + 1, (kt + 1) & 1);
            asm volatile("cp.async.wait_group 1;");
        } else {
            asm volatile("cp.async.wait_group 0;");
        }
        __syncthreads();

        const float* as = sm + (kt & 1) * STAGE_FLOATS;
        const float* bs = sm + (2 + (kt & 1)) * STAGE_FLOATS;

        #pragma unroll
        for (int ks = 0; ks < 4; ks++) {
            int kk = ks * 8;
            uint32_t a[4][4];
            #pragma unroll
            for (int mt = 0; mt < 4; mt++) {
                int mrow = wm + mt * 16;
                a[mt][0] = __float_as_uint(as[(mrow + r) * SM_STRIDE + kk + cc]);
                a[mt][1] = __float_as_uint(as[(mrow + r + 8) * SM_STRIDE + kk + cc]);
                a[mt][2] = __float_as_uint(as[(mrow + r) * SM_STRIDE + kk + cc + 4]);
                a[mt][3] = __float_as_uint(as[(mrow + r + 8) * SM_STRIDE + kk + cc + 4]);
            }
            uint32_t b[4][2];
            #pragma unroll
            for (int nt = 0; nt < 4; nt++) {
                int nrow = wn + nt * 8 + r;
                b[nt][0] = __float_as_uint(bs[nrow * SM_STRIDE + kk + cc]);
                b[nt][1] = __float_as_uint(bs[nrow * SM_STRIDE + kk + cc + 4]);
            }
            #pragma unroll
            for (int mt = 0; mt < 4; mt++)
                #pragma unroll
                for (int nt = 0; nt < 4; nt++)
                    mma_tf32(c[mt][nt], a[mt][0], a[mt][1], a[mt][2], a[mt][3],
                             b[nt][0], b[nt][1]);
        }
        __syncthreads();
    }

    // epilogue
    #pragma unroll
    for (int mt = 0; mt < 4; mt++) {
        int gm0 = bM + wm + mt * 16 + r;
        #pragma unroll
        for (int nt = 0; nt < 4; nt++) {
            int gn = bN + wn + nt * 8 + cc * 2;
            float2 v0 = make_float2(c[mt][nt][0], c[mt][nt][1]);
            float2 v1 = make_float2(c[mt][nt][2], c[mt][nt][3]);
            if (mode) {
                float bx = bias[gn], by = bias[gn + 1];
                v0.x = to_tf32(fmaxf(v0.x + bx, 0.f)); v0.y = to_tf32(fmaxf(v0.y + by, 0.f));
                v1.x = to_tf32(fmaxf(v1.x + bx, 0.f)); v1.y = to_tf32(fmaxf(v1.y + by, 0.f));
                if (gm0 < M)     *(float2*)(outf + (size_t)gm0 * 256 + gn) = v0;
                if (gm0 + 8 < M) *(float2*)(outf + (size_t)(gm0 + 8) * 256 + gn) = v1;
            } else if (bN == 0) {
                // aggregated half -> bf16 gather table
                __nv_bfloat162 p0 = __floats2bfloat162_rn(v0.x, v0.y);
                __nv_bfloat162 p1 = __floats2bfloat162_rn(v1.x, v1.y);
                if (gm0 < M)     *(__nv_bfloat162*)(g_P16 + (size_t)gm0 * 128 + gn) = p0;
                if (gm0 + 8 < M) *(__nv_bfloat162*)(g_P16 + (size_t)(gm0 + 8) * 128 + gn) = p1;
            } else {
                // self half -> fp32 (exact)
                int ln = gn - 128;
                if (gm0 < M)     *(float2*)(outf + (size_t)gm0 * 128 + ln) = v0;
                if (gm0 + 8 < M) *(float2*)(outf + (size_t)(gm0 + 8) * 128 + ln) = v1;
            }
        }
    }
}

// ---------------- layer-2 epilogue: 2 warps per node -----------------------
// out = mean_j P16[j] + Pself[i] + b2
__global__ void final_kernel(const float* __restrict__ Pself, const float* __restrict__ b2,
                             float* __restrict__ out) {
    __shared__ float4 s_acc[4][32];
    int wid = threadIdx.x >> 5;
    int pair = wid >> 1, sub = wid & 1;
    int lane = threadIdx.x & 31;
    int node = blockIdx.x * 4 + pair;          // always < NNODES
    int start = node ? g_rowstart[node - 1] : 0;
    int end = g_rowstart[node];

    float4 acc = make_float4(0.f, 0.f, 0.f, 0.f);
    int e = start + sub;
    for (; e + 6 < end; e += 8) {
        int s0 = g_csr_src[e],     s1 = g_csr_src[e + 2];
        int s2 = g_csr_src[e + 4], s3 = g_csr_src[e + 6];
        uint2 q0 = ((const uint2*)(g_P16 + (size_t)s0 * 128))[lane];
        uint2 q1 = ((const uint2*)(g_P16 + (size_t)s1 * 128))[lane];
        uint2 q2 = ((const uint2*)(g_P16 + (size_t)s2 * 128))[lane];
        uint2 q3 = ((const uint2*)(g_P16 + (size_t)s3 * 128))[lane];
        acc_bf16(acc, q0); acc_bf16(acc, q1); acc_bf16(acc, q2); acc_bf16(acc, q3);
    }
    for (; e < end; e += 2) {
        uint2 q = ((const uint2*)(g_P16 + (size_t)g_csr_src[e] * 128))[lane];
        acc_bf16(acc, q);
    }
    if (sub == 1) s_acc[pair][lane] = acc;
    __syncthreads();
    if (sub == 0) {
        float4 o = s_acc[pair][lane];
        acc.x += o.x; acc.y += o.y; acc.z += o.z; acc.w += o.w;
        int deg = end - start;
        float inv = (deg > 0) ? 1.0f / (float)deg : 0.0f;
        float4 self = ((const float4*)(Pself + (size_t)node * 128))[lane];
        float4 bb = ((const float4*)b2)[lane];
        float4 ov;
        ov.x = acc.x * inv + self.x + bb.x;
        ov.y = acc.y * inv + self.y + bb.y;
        ov.z = acc.z * inv + self.z + bb.z;
        ov.w = acc.w * inv + self.w + bb.w;
        ((float4*)(out + (size_t)node * 128))[lane] = ov;
    }
}

// ---------------- launch ----------------
extern "C" void kernel_launch(void* const* d_in, const int* in_sizes, int n_in,
                              void* d_out, int out_size) {
    const float* x    = (const float*)d_in[0];
    const void*  eidx = d_in[1];
    const float* W1_l = (const float*)d_in[2];
    const float* b1   = (const float*)d_in[3];
    const float* W1_r = (const float*)d_in[4];
    const float* W2_l = (const float*)d_in[5];
    const float* b2   = (const float*)d_in[6];
    const float* W2_r = (const float*)d_in[7];
    float* out = (float*)d_out;

    long long E = (long long)in_sizes[1] / 2;

    float *cat, *h;
    void* zptr;
    cudaGetSymbolAddress((void**)&cat, g_cat);
    cudaGetSymbolAddress((void**)&h,   g_h);
    cudaGetSymbolAddress(&zptr, g_z);

    float *Bp1, *Bp2;
    cudaGetSymbolAddress((void**)&Bp1, g_Bp1);
    cudaGetSymbolAddress((void**)&Bp2, g_Bp2);

    cudaFuncSetAttribute(gemm_tf32_kernel,
                         cudaFuncAttributeMaxDynamicSharedMemorySize, GEMM_SMEM_BYTES);

    // fused prologue grid: count_deg | pack | convert_x
    int conv_blocks = (NNODES * 32 + 255) / 256;          // 6250
    int fused_blocks = EB + 512 + conv_blocks;

    // 1. memset + fused prologue + scan + scatter
    cudaMemsetAsync(zptr, 0, sizeof(ZeroRegion));
    fused_prologue_kernel<<<fused_blocks, 256>>>(eidx, E, x, W1_l, W1_r, W2_l, W2_r);
    scan_lookback_kernel<<<SBLK, 1024>>>(SBLK);
    scatter_kernel<<<EB, 256>>>(eidx, E);

    // 2. layer 1
    int ab = NNODES / 4;                                  // 12500 blocks, 2 warps/node
    agg_cat_kernel<<<ab, 256>>>(x, cat);
    dim3 ggrid(2, (NNODES + 127) / 128);
    gemm_tf32_kernel<<<ggrid, 256, GEMM_SMEM_BYTES>>>(cat, Bp1, b1, h, NNODES, 1);

    // 3. layer 2: P halves (bf16 agg table + fp32 self), then aggregate+combine
    gemm_tf32_kernel<<<ggrid, 256, GEMM_SMEM_BYTES>>>(h, Bp2, nullptr, cat, NNODES, 0);
    final_kernel<<<ab, 256>>>(cat, b2, out);
}

// round 17
// speedup vs baseline: 1.0760x; 1.0760x over previous
#include <cuda_runtime.h>
#include <cuda_bf16.h>
#include <cstdint>

#define NNODES 50000
#define EMAX   800000
#define SBLK   ((NNODES + 1023) / 1024)   // 49 scan blocks
#define EB     ((EMAX + 255) / 256)       // 3125 edge blocks (E is always 800000)

// ---------------- device scratch ----------------
// Self-cleaning state: deg[] is zeroed by scan_lookback after reading (and is
// zero-initialized at module load); lb[] is reset by scatter block 0.
// No memset node needed.
struct ScratchInts {
    int deg[NNODES];
    unsigned long long lb[64];            // lookback words: (val<<2)|state
};
__device__ ScratchInts g_z;               // zero-initialized at load

__device__ int g_rowstart[NNODES + 1];
__device__ int g_csr_src[EMAX];
__device__ __align__(128) float g_cat[(size_t)NNODES * 256]; // L1 A=[agg|x]; L2 reuse: Pself fp32 [N,128]
__device__ __align__(128) float g_h[(size_t)NNODES * 256];   // hidden activations (tf32-rounded)
__device__ __align__(128) __nv_bfloat16 g_x16[(size_t)NNODES * 128]; // bf16 copy of x (gather table)
__device__ __align__(128) __nv_bfloat16 g_P16[(size_t)NNODES * 128]; // bf16 agg-half of P (gather table)
__device__ __align__(128) float g_Bp1[256 * 256];            // packed tf32 weights layer1
__device__ __align__(128) float g_Bp2[256 * 256];            // packed tf32 weights layer2

__device__ __forceinline__ float to_tf32(float x) {
    float r;
    asm("cvt.rna.tf32.f32 %0, %1;" : "=f"(r) : "f"(x));
    return r;
}

// per-block dtype detect: int32 data read as u64 has nonzero high halves
__device__ __forceinline__ int block_detect_is32(const void* eidx) {
    __shared__ int s_is32;
    if (threadIdx.x < 32) {
        const unsigned long long* p = (const unsigned long long*)eidx;
        bool big = (p[threadIdx.x] > 0xFFFFFFFFULL) ||
                   (p[threadIdx.x + 32] > 0xFFFFFFFFULL);
        unsigned bal = __ballot_sync(0xFFFFFFFFu, big);
        if (threadIdx.x == 0) s_is32 = bal ? 1 : 0;
    }
    __syncthreads();
    return s_is32;
}

__device__ __forceinline__ long long edge_val(const void* eidx, long long idx, int is32) {
    if (is32) return (long long)((const int*)eidx)[idx];
    return ((const long long*)eidx)[idx];
}

// ---------------- fused prologue: count_deg | pack | convert_x -------------
__global__ void fused_prologue_kernel(
    const void* eidx, long long E, const float* __restrict__ x,
    const float* __restrict__ W1l, const float* __restrict__ W1r,
    const float* __restrict__ W2l, const float* __restrict__ W2r)
{
    int b = blockIdx.x;
    if (b < EB) {
        int is32 = block_detect_is32(eidx);
        long long e = (long long)b * 256 + threadIdx.x;
        if (e < E) {
            int d = (int)edge_val(eidx, E + e, is32);
            atomicAdd(&g_z.deg[d], 1);
        }
    } else if (b < EB + 512) {
        int i = (b - EB) * 256 + threadIdx.x;
        if (i < 65536) {
            int n = i >> 8, k = i & 255;
            float v = (k < 128) ? W1l[n * 128 + k] : W1r[n * 128 + (k - 128)];
            g_Bp1[i] = to_tf32(v);
        } else {
            int j = i - 65536;
            int n = j >> 8, k = j & 255;
            float v = (n < 128) ? W2l[n * 256 + k] : W2r[(n - 128) * 256 + k];
            g_Bp2[j] = to_tf32(v);
        }
    } else {
        int i = (b - EB - 512) * 256 + threadIdx.x;   // one per 4 elems
        if (i < NNODES * 32) {
            float4 v = ((const float4*)x)[i];
            __nv_bfloat162 a = __floats2bfloat162_rn(v.x, v.y);
            __nv_bfloat162 bb = __floats2bfloat162_rn(v.z, v.w);
            uint2 q;
            q.x = *(uint32_t*)&a;
            q.y = *(uint32_t*)&bb;
            ((uint2*)g_x16)[i] = q;
        }
    }
}

// single-pass scan with decoupled lookback (49 blocks, all co-resident).
// Also zeroes deg[] after reading so the next graph replay starts clean.
__global__ void scan_lookback_kernel(int nblk) {
    __shared__ int wsum[32];
    __shared__ int s_run;
    int b = blockIdx.x, t = threadIdx.x;
    int i = b * 1024 + t;
    int v = 0;
    if (i < NNODES) { v = g_z.deg[i]; g_z.deg[i] = 0; }   // read + self-clean
    int lane = t & 31, wid = t >> 5;
    int x = v;
    #pragma unroll
    for (int o = 1; o < 32; o <<= 1) {
        int y = __shfl_up_sync(0xFFFFFFFFu, x, o);
        if (lane >= o) x += y;
    }
    if (lane == 31) wsum[wid] = x;
    __syncthreads();
    if (wid == 0) {
        int s = wsum[lane];
        #pragma unroll
        for (int o = 1; o < 32; o <<= 1) {
            int y = __shfl_up_sync(0xFFFFFFFFu, s, o);
            if (lane >= o) s += y;
        }
        wsum[lane] = s;
    }
    __syncthreads();
    int blockSum = wsum[31];
    int excl = x - v + (wid ? wsum[wid - 1] : 0);

    if (t == 0) {
        atomicExch(&g_z.lb[b], ((unsigned long long)blockSum << 2) | 1ULL);
        long long run = 0;
        for (int j = b - 1; j >= 0; ) {
            unsigned long long w;
            do { w = atomicAdd(&g_z.lb[j], 0ULL); } while ((w & 3ULL) == 0ULL);
            run += (long long)(w >> 2);
            if ((w & 3ULL) == 2ULL) break;
            j--;
        }
        atomicExch(&g_z.lb[b], ((unsigned long long)(blockSum + run) << 2) | 2ULL);
        s_run = (int)run;
        if (b == nblk - 1) g_rowstart[NNODES] = (int)run + blockSum;
    }
    __syncthreads();
    if (i < NNODES) g_rowstart[i] = excl + s_run;
}

// cursor-free scatter: rowstart doubles as the insertion cursor.
// After this kernel, g_rowstart[d] == old exclusive prefix of (d+1),
// so consumers use start = rowstart[node-1] (0 for node 0), end = rowstart[node].
// Block 0 also resets the lookback words for the next replay.
__global__ void scatter_kernel(const void* eidx, long long E) {
    if (blockIdx.x == 0 && threadIdx.x < 64)
        g_z.lb[threadIdx.x] = 0ULL;       // self-clean for next replay
    int is32 = block_detect_is32(eidx);
    long long e = (long long)blockIdx.x * blockDim.x + threadIdx.x;
    if (e >= E) return;
    int s = (int)edge_val(eidx, e, is32);
    int d = (int)edge_val(eidx, E + e, is32);
    int pos = atomicAdd(&g_rowstart[d], 1);
    g_csr_src[pos] = s;
}

// ---------------- gather helper: 4 bf16 (uint2) -> float4 accumulate ------
__device__ __forceinline__ void acc_bf16(float4& acc, uint2 q) {
    float2 f0 = __bfloat1622float2(*(__nv_bfloat162*)&q.x);
    float2 f1 = __bfloat1622float2(*(__nv_bfloat162*)&q.y);
    acc.x += f0.x; acc.y += f0.y; acc.z += f1.x; acc.w += f1.y;
}

// ---------------- layer-1 aggregation (proven R14 shape) -------------------
__global__ void agg_cat_kernel(const float* __restrict__ x, float* __restrict__ cat) {
    int node = blockIdx.x * (blockDim.x >> 5) + (threadIdx.x >> 5);
    if (node >= NNODES) return;
    int lane = threadIdx.x & 31;
    int start = node ? g_rowstart[node - 1] : 0;
    int end = g_rowstart[node];
    float4 acc = make_float4(0.f, 0.f, 0.f, 0.f);
    int e = start;
    for (; e + 3 < end; e += 4) {
        int s0 = g_csr_src[e], s1 = g_csr_src[e + 1];
        int s2 = g_csr_src[e + 2], s3 = g_csr_src[e + 3];
        uint2 q0 = ((const uint2*)(g_x16 + (size_t)s0 * 128))[lane];
        uint2 q1 = ((const uint2*)(g_x16 + (size_t)s1 * 128))[lane];
        uint2 q2 = ((const uint2*)(g_x16 + (size_t)s2 * 128))[lane];
        uint2 q3 = ((const uint2*)(g_x16 + (size_t)s3 * 128))[lane];
        acc_bf16(acc, q0); acc_bf16(acc, q1); acc_bf16(acc, q2); acc_bf16(acc, q3);
    }
    for (; e < end; e++) {
        uint2 q = ((const uint2*)(g_x16 + (size_t)g_csr_src[e] * 128))[lane];
        acc_bf16(acc, q);
    }
    int deg = end - start;
    float inv = (deg > 0) ? 1.0f / (float)deg : 0.0f;
    float4* crow = (float4*)(cat + (size_t)node * 256);
    crow[lane] = make_float4(to_tf32(acc.x * inv), to_tf32(acc.y * inv),
                             to_tf32(acc.z * inv), to_tf32(acc.w * inv));
    float4 xs = ((const float4*)(x + (size_t)node * 128))[lane];   // self: exact fp32
    crow[32 + lane] = make_float4(to_tf32(xs.x), to_tf32(xs.y),
                                  to_tf32(xs.z), to_tf32(xs.w));
}

// ---------------- tf32 tensor-core GEMM, 2-stage cp.async pipeline ----------
// A[M,256] @ B[256,256]^T. mode=1: +bias,+relu,+tf32 round -> outf[M,256].
// mode=0 (layer2): bN==0 half -> bf16 to g_P16[M,128]; bN==128 half -> fp32 outf[M,128].
#define SM_STRIDE 36
#define STAGE_FLOATS (128 * SM_STRIDE)
#define GEMM_SMEM_BYTES (4 * STAGE_FLOATS * 4)

__device__ __forceinline__ void mma_tf32(float c[4], uint32_t a0, uint32_t a1,
                                         uint32_t a2, uint32_t a3,
                                         uint32_t b0, uint32_t b1) {
    asm volatile(
        "mma.sync.aligned.m16n8k8.row.col.f32.tf32.tf32.f32 "
        "{%0,%1,%2,%3}, {%4,%5,%6,%7}, {%8,%9}, {%0,%1,%2,%3};"
        : "+f"(c[0]), "+f"(c[1]), "+f"(c[2]), "+f"(c[3])
        : "r"(a0), "r"(a1), "r"(a2), "r"(a3), "r"(b0), "r"(b1));
}

__global__ void __launch_bounds__(256, 2) gemm_tf32_kernel(
    const float* __restrict__ A, const float* __restrict__ B,
    const float* __restrict__ bias, float* __restrict__ outf,
    int M, int mode)
{
    extern __shared__ float sm[];

    int tid = threadIdx.x;
    int lane = tid & 31, warp = tid >> 5;
    int wm = (warp >> 2) * 64;
    int wn = (warp & 3) * 32;
    int bM = blockIdx.y * 128;
    int bN = blockIdx.x * 128;
    int r = lane >> 2, cc = lane & 3;

    uint32_t sbase = (uint32_t)__cvta_generic_to_shared(sm);

    float c[4][4][4];
    #pragma unroll
    for (int mt = 0; mt < 4; mt++)
        #pragma unroll
        for (int nt = 0; nt < 4; nt++)
            #pragma unroll
            for (int q = 0; q < 4; q++) c[mt][nt][q] = 0.f;

    auto load_tile = [&](int kt, int s) {
        int k0 = kt * 32;
        #pragma unroll
        for (int i = 0; i < 4; i++) {
            int idx = i * 256 + tid;       // 0..1023
            int m = idx >> 3;              // 0..127
            int k4 = (idx & 7) * 4;        // 0..28
            const float* ga = A + (size_t)(bM + m) * 256 + k0 + k4;
            uint32_t da = sbase + (uint32_t)((s * STAGE_FLOATS + m * SM_STRIDE + k4) * 4);
            int sz = (bM + m < M) ? 16 : 0;
            asm volatile("cp.async.cg.shared.global [%0], [%1], 16, %2;"
                         :: "r"(da), "l"(ga), "r"(sz));
            const float* gb = B + (size_t)(bN + m) * 256 + k0 + k4;
            uint32_t db = sbase + (uint32_t)(((2 + s) * STAGE_FLOATS + m * SM_STRIDE + k4) * 4);
            asm volatile("cp.async.cg.shared.global [%0], [%1], 16, %2;"
                         :: "r"(db), "l"(gb), "r"(16));
        }
        asm volatile("cp.async.commit_group;");
    };

    load_tile(0, 0);

    for (int kt = 0; kt < 8; kt++) {
        if (kt + 1 < 8) {
            load_tile(kt + 1, (kt + 1) & 1);
            asm volatile("cp.async.wait_group 1;");
        } else {
            asm volatile("cp.async.wait_group 0;");
        }
        __syncthreads();

        const float* as = sm + (kt & 1) * STAGE_FLOATS;
        const float* bs = sm + (2 + (kt & 1)) * STAGE_FLOATS;

        #pragma unroll
        for (int ks = 0; ks < 4; ks++) {
            int kk = ks * 8;
            uint32_t a[4][4];
            #pragma unroll
            for (int mt = 0; mt < 4; mt++) {
                int mrow = wm + mt * 16;
                a[mt][0] = __float_as_uint(as[(mrow + r) * SM_STRIDE + kk + cc]);
                a[mt][1] = __float_as_uint(as[(mrow + r + 8) * SM_STRIDE + kk + cc]);
                a[mt][2] = __float_as_uint(as[(mrow + r) * SM_STRIDE + kk + cc + 4]);
                a[mt][3] = __float_as_uint(as[(mrow + r + 8) * SM_STRIDE + kk + cc + 4]);
            }
            uint32_t b[4][2];
            #pragma unroll
            for (int nt = 0; nt < 4; nt++) {
                int nrow = wn + nt * 8 + r;
                b[nt][0] = __float_as_uint(bs[nrow * SM_STRIDE + kk + cc]);
                b[nt][1] = __float_as_uint(bs[nrow * SM_STRIDE + kk + cc + 4]);
            }
            #pragma unroll
            for (int mt = 0; mt < 4; mt++)
                #pragma unroll
                for (int nt = 0; nt < 4; nt++)
                    mma_tf32(c[mt][nt], a[mt][0], a[mt][1], a[mt][2], a[mt][3],
                             b[nt][0], b[nt][1]);
        }
        __syncthreads();
    }

    // epilogue
    #pragma unroll
    for (int mt = 0; mt < 4; mt++) {
        int gm0 = bM + wm + mt * 16 + r;
        #pragma unroll
        for (int nt = 0; nt < 4; nt++) {
            int gn = bN + wn + nt * 8 + cc * 2;
            float2 v0 = make_float2(c[mt][nt][0], c[mt][nt][1]);
            float2 v1 = make_float2(c[mt][nt][2], c[mt][nt][3]);
            if (mode) {
                float bx = bias[gn], by = bias[gn + 1];
                v0.x = to_tf32(fmaxf(v0.x + bx, 0.f)); v0.y = to_tf32(fmaxf(v0.y + by, 0.f));
                v1.x = to_tf32(fmaxf(v1.x + bx, 0.f)); v1.y = to_tf32(fmaxf(v1.y + by, 0.f));
                if (gm0 < M)     *(float2*)(outf + (size_t)gm0 * 256 + gn) = v0;
                if (gm0 + 8 < M) *(float2*)(outf + (size_t)(gm0 + 8) * 256 + gn) = v1;
            } else if (bN == 0) {
                // aggregated half -> bf16 gather table
                __nv_bfloat162 p0 = __floats2bfloat162_rn(v0.x, v0.y);
                __nv_bfloat162 p1 = __floats2bfloat162_rn(v1.x, v1.y);
                if (gm0 < M)     *(__nv_bfloat162*)(g_P16 + (size_t)gm0 * 128 + gn) = p0;
                if (gm0 + 8 < M) *(__nv_bfloat162*)(g_P16 + (size_t)(gm0 + 8) * 128 + gn) = p1;
            } else {
                // self half -> fp32 (exact)
                int ln = gn - 128;
                if (gm0 < M)     *(float2*)(outf + (size_t)gm0 * 128 + ln) = v0;
                if (gm0 + 8 < M) *(float2*)(outf + (size_t)(gm0 + 8) * 128 + ln) = v1;
            }
        }
    }
}

// ---------------- layer-2 epilogue (proven R14 shape) ----------------------
// out = mean_j P16[j] + Pself[i] + b2
__global__ void final_kernel(const float* __restrict__ Pself, const float* __restrict__ b2,
                             float* __restrict__ out) {
    int node = blockIdx.x * (blockDim.x >> 5) + (threadIdx.x >> 5);
    if (node >= NNODES) return;
    int lane = threadIdx.x & 31;
    int start = node ? g_rowstart[node - 1] : 0;
    int end = g_rowstart[node];
    float4 acc = make_float4(0.f, 0.f, 0.f, 0.f);
    int e = start;
    for (; e + 3 < end; e += 4) {
        int s0 = g_csr_src[e], s1 = g_csr_src[e + 1];
        int s2 = g_csr_src[e + 2], s3 = g_csr_src[e + 3];
        uint2 q0 = ((const uint2*)(g_P16 + (size_t)s0 * 128))[lane];
        uint2 q1 = ((const uint2*)(g_P16 + (size_t)s1 * 128))[lane];
        uint2 q2 = ((const uint2*)(g_P16 + (size_t)s2 * 128))[lane];
        uint2 q3 = ((const uint2*)(g_P16 + (size_t)s3 * 128))[lane];
        acc_bf16(acc, q0); acc_bf16(acc, q1); acc_bf16(acc, q2); acc_bf16(acc, q3);
    }
    for (; e < end; e++) {
        uint2 q = ((const uint2*)(g_P16 + (size_t)g_csr_src[e] * 128))[lane];
        acc_bf16(acc, q);
    }
    int deg = end - start;
    float inv = (deg > 0) ? 1.0f / (float)deg : 0.0f;
    float4 self = ((const float4*)(Pself + (size_t)node * 128))[lane];
    float4 bb = ((const float4*)b2)[lane];
    float4 o;
    o.x = acc.x * inv + self.x + bb.x;
    o.y = acc.y * inv + self.y + bb.y;
    o.z = acc.z * inv + self.z + bb.z;
    o.w = acc.w * inv + self.w + bb.w;
    ((float4*)(out + (size_t)node * 128))[lane] = o;
}

// ---------------- launch ----------------
extern "C" void kernel_launch(void* const* d_in, const int* in_sizes, int n_in,
                              void* d_out, int out_size) {
    const float* x    = (const float*)d_in[0];
    const void*  eidx = d_in[1];
    const float* W1_l = (const float*)d_in[2];
    const float* b1   = (const float*)d_in[3];
    const float* W1_r = (const float*)d_in[4];
    const float* W2_l = (const float*)d_in[5];
    const float* b2   = (const float*)d_in[6];
    const float* W2_r = (const float*)d_in[7];
    float* out = (float*)d_out;

    long long E = (long long)in_sizes[1] / 2;

    float *cat, *h;
    cudaGetSymbolAddress((void**)&cat, g_cat);
    cudaGetSymbolAddress((void**)&h,   g_h);

    float *Bp1, *Bp2;
    cudaGetSymbolAddress((void**)&Bp1, g_Bp1);
    cudaGetSymbolAddress((void**)&Bp2, g_Bp2);

    cudaFuncSetAttribute(gemm_tf32_kernel,
                         cudaFuncAttributeMaxDynamicSharedMemorySize, GEMM_SMEM_BYTES);

    // fused prologue grid: count_deg | pack | convert_x
    int conv_blocks = (NNODES * 32 + 255) / 256;          // 6250
    int fused_blocks = EB + 512 + conv_blocks;

    // 1. prologue + scan + scatter (self-cleaning state; no memset node)
    fused_prologue_kernel<<<fused_blocks, 256>>>(eidx, E, x, W1_l, W1_r, W2_l, W2_r); // 0
    scan_lookback_kernel<<<SBLK, 1024>>>(SBLK);                                        // 1
    scatter_kernel<<<EB, 256>>>(eidx, E);                                              // 2

    // 2. layer 1
    int ab = (NNODES + 7) / 8;
    agg_cat_kernel<<<ab, 256>>>(x, cat);                                               // 3
    dim3 ggrid(2, (NNODES + 127) / 128);
    gemm_tf32_kernel<<<ggrid, 256, GEMM_SMEM_BYTES>>>(cat, Bp1, b1, h, NNODES, 1);     // 4 <- ncu

    // 3. layer 2: P halves (bf16 agg table + fp32 self), then aggregate+combine
    gemm_tf32_kernel<<<ggrid, 256, GEMM_SMEM_BYTES>>>(h, Bp2, nullptr, cat, NNODES, 0);// 5
    final_kernel<<<ab, 256>>>(cat, b2, out);                                           // 6
}